// round 8
// baseline (speedup 1.0000x reference)
#include <cuda_runtime.h>
#include <math.h>
#include <stdint.h>

// ---------------------------------------------------------------------------
// Problem constants
// ---------------------------------------------------------------------------
#define NSAMP  8192
#define NDIMT  3072
#define NKER   64
#define NSUB   48
#define MKNOT  200
#define NTRT   3072

// ---------------------------------------------------------------------------
// Device scratch (static only)
// ---------------------------------------------------------------------------
__device__ float g_Q  [NKER * NSUB * NSUB];   // [k][j][i]
__device__ float g_QT [NKER * NSUB * NSUB];   // [k][i][j]
__device__ float g_xx [NTRT * MKNOT];
__device__ float g_yy [NTRT * MKNOT];
__device__ float g_dl [NTRT * MKNOT];
__device__ float g_lj [NKER * NSAMP];
__device__ unsigned char g_lut[NTRT * 256];
__device__ float g_lxlo[NTRT];
__device__ float g_livw[NTRT];

// ---------------------------------------------------------------------------
// f32x2 helpers (packed fp32 — exact fp32 per lane)
// ---------------------------------------------------------------------------
__device__ __forceinline__ void ffma2(unsigned long long& acc,
                                      unsigned long long a, unsigned long long b) {
    asm("fma.rn.f32x2 %0, %1, %2, %0;" : "+l"(acc) : "l"(a), "l"(b));
}
__device__ __forceinline__ unsigned long long splat2(float v) {
    unsigned long long r;
    asm("mov.b64 %0, {%1, %1};" : "=l"(r) : "f"(v));
    return r;
}
__device__ __forceinline__ float2 unpk2(unsigned long long v) {
    float2 r;
    asm("mov.b64 {%0, %1}, %2;" : "=f"(r.x), "=f"(r.y) : "l"(v));
    return r;
}

// ---------------------------------------------------------------------------
// Kernel 1: per-patch MGS QR (positive diagonal), writes Q and Q^T.
// ---------------------------------------------------------------------------
__global__ void orth_kernel(const float* __restrict__ A_raw) {
    const int k   = blockIdx.x;
    const int tid = threadIdx.x;
    __shared__ float qcol[NSUB];

    float col[NSUB];
    const float* Ab = A_raw + k * (NSUB * NSUB);
    if (tid < NSUB) {
#pragma unroll
        for (int r = 0; r < NSUB; ++r) col[r] = Ab[r * NSUB + tid];
    }

    for (int c = 0; c < NSUB; ++c) {
        if (tid == c) {
            float nrm = 0.f;
#pragma unroll
            for (int r = 0; r < NSUB; ++r) nrm += col[r] * col[r];
            float inv = 1.0f / sqrtf(nrm);
#pragma unroll
            for (int r = 0; r < NSUB; ++r) { col[r] *= inv; qcol[r] = col[r]; }
        }
        __syncthreads();
        if (tid < NSUB) {
            if (tid == c) {
                float* gq  = g_Q  + k * (NSUB * NSUB);
                float* gqt = g_QT + k * (NSUB * NSUB);
#pragma unroll
                for (int r = 0; r < NSUB; ++r) {
                    gq [r * NSUB + c] = qcol[r];
                    gqt[c * NSUB + r] = qcol[r];
                }
            } else if (tid > c) {
                float dot = 0.f;
#pragma unroll
                for (int r = 0; r < NSUB; ++r) dot += qcol[r] * col[r];
#pragma unroll
                for (int r = 0; r < NSUB; ++r) col[r] -= dot * qcol[r];
            }
        }
        __syncthreads();
    }
}

// ---------------------------------------------------------------------------
// Kernel 2: knot tables via warp scans.
// ---------------------------------------------------------------------------
__global__ void knots_kernel(const float* __restrict__ x0,
                             const float* __restrict__ logdx,
                             const float* __restrict__ y0,
                             const float* __restrict__ logdy,
                             const float* __restrict__ logderiv) {
    const int warp = (blockIdx.x * blockDim.x + threadIdx.x) >> 5;
    const int lane = threadIdx.x & 31;
    if (warp >= NTRT) return;

    {
        float carry = x0[warp];
        if (lane == 0) g_xx[warp * MKNOT] = carry;
        const float* src = logdx + (size_t)warp * (MKNOT - 1);
        for (int c = 0; c < MKNOT - 1; c += 32) {
            int m = c + lane;
            float v = (m < MKNOT - 1) ? expf(src[m]) : 0.f;
#pragma unroll
            for (int off = 1; off < 32; off <<= 1) {
                float o = __shfl_up_sync(0xffffffffu, v, off);
                if (lane >= off) v += o;
            }
            if (m < MKNOT - 1) g_xx[warp * MKNOT + m + 1] = carry + v;
            carry += __shfl_sync(0xffffffffu, v, 31);
        }
    }
    {
        float carry = y0[warp];
        if (lane == 0) g_yy[warp * MKNOT] = carry;
        const float* src = logdy + (size_t)warp * (MKNOT - 1);
        for (int c = 0; c < MKNOT - 1; c += 32) {
            int m = c + lane;
            float v = (m < MKNOT - 1) ? expf(src[m]) : 0.f;
#pragma unroll
            for (int off = 1; off < 32; off <<= 1) {
                float o = __shfl_up_sync(0xffffffffu, v, off);
                if (lane >= off) v += o;
            }
            if (m < MKNOT - 1) g_yy[warp * MKNOT + m + 1] = carry + v;
            carry += __shfl_sync(0xffffffffu, v, 31);
        }
    }
    for (int m = lane; m < MKNOT; m += 32)
        g_dl[warp * MKNOT + m] = expf(logderiv[(size_t)warp * MKNOT + m]);
}

// ---------------------------------------------------------------------------
// Kernel 2b: per-coordinate 256-bin search LUT.
// ---------------------------------------------------------------------------
__global__ void lut_kernel() {
    const int warp = (blockIdx.x * blockDim.x + threadIdx.x) >> 5;
    const int lane = threadIdx.x & 31;
    if (warp >= NTRT) return;
    const float* xr = g_xx + (size_t)warp * MKNOT;
    float xlo = xr[0], xhi = xr[MKNOT - 1];
    float binw = (xhi - xlo) * (1.0f / 256.0f);
    if (lane == 0) { g_lxlo[warp] = xlo; g_livw[warp] = 256.0f / (xhi - xlo); }
#pragma unroll
    for (int t = 0; t < 8; ++t) {
        int q = lane + 32 * t;
        float L = xlo + q * binw;
        int lo = 0, hi = MKNOT;
        while (lo < hi) { int mid = (lo + hi) >> 1; if (xr[mid] < L) lo = mid + 1; else hi = mid; }
        g_lut[(size_t)warp * 256 + q] = (unsigned char)lo;
    }
}

// ---------------------------------------------------------------------------
// Kernel 3: fused pipeline. 768 threads, 24 warps.
// ---------------------------------------------------------------------------
#define TPB      768
#define ROWS_IT  128
#define ITERS    4
#define RST      130

// smem layout (float offsets)
#define SO_X   0                        // 48*200 x-knots (full-bank for search)
#define SO_YD  (SO_X + 48*200)          // 9600 : 48*200 float2 {y,d}
#define SO_Q   (SO_YD + 48*200*2)       // 28800 : [j][i]
#define SO_QT  (SO_Q  + 48*48)          // 31104 : [i][j]
#define SO_V   (SO_QT + 48*48)          // 33408 : gather buffer (becomes V+W)
#define SO_S   (SO_V  + 48*RST)         // 39648 : spline output
#define SO_LJ  (SO_S  + 48*RST)         // 45888 : [12][128]
#define SO_XLO (SO_LJ + 12*128)         // 47424
#define SO_IVW (SO_XLO + 48)            // 47472
#define SO_RI  (SO_IVW + 48)            // 47520
#define SO_LUT (SO_RI + 48)             // 47568 : uint8[12288]
#define SMEM_FLOATS (SO_LUT + 3072)     // 50640
#define SMEM_BYTES  (SMEM_FLOATS * 4)   // 202,560 B

__device__ __forceinline__ float rq_eval(float x,
                                         const float* __restrict__ xr,
                                         const float2* __restrict__ yd,
                                         const unsigned char* __restrict__ lut,
                                         float xlo, float ivw, float& dv) {
    int q = __float2int_rd((x - xlo) * ivw);
    q = min(max(q, 0), 255);
    int idx = lut[q];
    while (idx > 0 && xr[idx - 1] >= x) --idx;
    while (idx < MKNOT && xr[idx] < x) ++idx;
    if (idx == 0) {
        float2 k0 = yd[0];
        dv = k0.y;
        return k0.x + dv * (x - xr[0]);
    }
    if (idx == MKNOT) {
        float2 km = yd[MKNOT - 1];
        dv = km.y;
        return km.x + dv * (x - xr[MKNOT - 1]);
    }
    const int kk = idx - 1;
    const float  xK = xr[kk], xK1 = xr[kk + 1];
    const float2 k0 = yd[kk], k1 = yd[kk + 1];   // (y, d)
    const float inv = __fdividef(1.f, xK1 - xK);
    float xi = fminf(fmaxf((x - xK) * inv, 0.f), 1.f);
    const float sl  = (k1.x - k0.x) * inv;
    const float xi1 = xi * (1.f - xi);
    const float den = sl + (k1.y + k0.y - 2.f * sl) * xi1;
    const float ivd = __fdividef(1.f, den);
    const float om  = 1.f - xi;
    dv = sl * sl * (k1.y * xi * xi + 2.f * sl * xi1 + k0.y * om * om) * ivd * ivd;
    return k0.x + (k1.x - k0.x) * (sl * xi * xi + k0.y * xi1) * ivd;
}

__global__ void __launch_bounds__(TPB, 1)
fused_kernel(const float* __restrict__ data, float* __restrict__ out) {
    extern __shared__ float sm[];
    int* ri = (int*)&sm[SO_RI];
    unsigned char* slut = (unsigned char*)&sm[SO_LUT];

    const int tid = threadIdx.x;
    const int k   = blockIdx.x;

    // ---- prologue --------------------------------------------------------
    {
        const float4* gq  = (const float4*)(g_Q  + k * (NSUB * NSUB));
        const float4* gqt = (const float4*)(g_QT + k * (NSUB * NSUB));
        float4* sq  = (float4*)&sm[SO_Q];
        float4* sqt = (float4*)&sm[SO_QT];
        for (int idx = tid; idx < NSUB * NSUB / 4; idx += TPB) {
            sq[idx]  = gq[idx];
            sqt[idx] = gqt[idx];
        }
        const float4* gx = (const float4*)(g_xx + (size_t)k * NSUB * MKNOT);
        float4* sx = (float4*)&sm[SO_X];
        for (int idx = tid; idx < NSUB * MKNOT / 4; idx += TPB) sx[idx] = gx[idx];
        // interleave y,d -> float2
        const float* gy = g_yy + (size_t)k * NSUB * MKNOT;
        const float* gd = g_dl + (size_t)k * NSUB * MKNOT;
        float2* syd = (float2*)&sm[SO_YD];
        for (int idx = tid; idx < NSUB * MKNOT; idx += TPB) {
            float2 v; v.x = gy[idx]; v.y = gd[idx];
            syd[idx] = v;
        }
        const int4* gl = (const int4*)(g_lut + (size_t)k * NSUB * 256);
        int4* sl = (int4*)slut;
        for (int idx = tid; idx < NSUB * 256 / 16; idx += TPB) sl[idx] = gl[idx];
        if (tid < NSUB) {
            sm[SO_XLO + tid] = g_lxlo[k * NSUB + tid];
            sm[SO_IVW + tid] = g_livw[k * NSUB + tid];
            int nh = k >> 3, nw = k & 7;
            int kh = tid / 12, rem = tid - kh * 12, kw = rem / 3, c = rem - kw * 3;
            int h = (nh * 4 + kh + 2) & 31;
            int w = (nw * 4 + kw + 2) & 31;
            ri[tid] = h * 96 + w * 3 + c;
        }
    }
    __syncthreads();

    const int jg = tid % 48;          // gather/scatter column
    const int rb = tid / 48;          // 0..15
    const int ig = tid >> 6;          // 0..11 : i/j tile group (4 wide)
    const int rg = tid & 63;          // 0..63 : r pair group
    const int i0 = ig * 4;
    const int r0 = rg * 2;

    for (int it = 0; it < ITERS; ++it) {
        const int nbase = blockIdx.y * (ROWS_IT * ITERS) + it * ROWS_IT;

        // ---- gather: V[j][r] = data[n, ridx[j]] ---------------------------
        {
            const int rid = ri[jg];
#pragma unroll
            for (int t = 0; t < 8; ++t) {
                int r = rb + 16 * t;
                sm[SO_V + jg * RST + r] = __ldg(&data[(size_t)(nbase + r) * NDIMT + rid]);
            }
        }
        __syncthreads();

        // ---- fwd GEMV (U in regs) + fused RQ spline -> S, logdet ----------
        {
            unsigned long long a0 = 0, a1 = 0, a2 = 0, a3 = 0;
#pragma unroll 8
            for (int j = 0; j < 48; ++j) {
                const float4 q = *(const float4*)&sm[SO_Q + j * 48 + i0];  // broadcast
                const unsigned long long v = *(const unsigned long long*)&sm[SO_V + j * RST + r0];
                ffma2(a0, splat2(q.x), v);
                ffma2(a1, splat2(q.y), v);
                ffma2(a2, splat2(q.z), v);
                ffma2(a3, splat2(q.w), v);
            }
            unsigned long long acc[4] = {a0, a1, a2, a3};
            float pa = 1.f, pb = 1.f;
#pragma unroll
            for (int s = 0; s < 4; ++s) {
                const int i = i0 + s;
                const float*  xr = &sm[SO_X + i * MKNOT];
                const float2* yd = (const float2*)&sm[SO_YD + (i * MKNOT) * 2];
                const unsigned char* lut = slut + i * 256;
                const float xlo = sm[SO_XLO + i];
                const float ivw = sm[SO_IVW + i];

                float2 xv = unpk2(acc[s]);            // U directly from regs
                float da, db;
                float ya = rq_eval(xv.x, xr, yd, lut, xlo, ivw, da);
                float yb = rq_eval(xv.y, xr, yd, lut, xlo, ivw, db);
                float2 sv; sv.x = ya - xv.x; sv.y = yb - xv.y;
                *(float2*)&sm[SO_S + i * RST + r0] = sv;
                pa *= da; pb *= db;
            }
            float2 lj2; lj2.x = __logf(pa); lj2.y = __logf(pb);
            *(float2*)&sm[SO_LJ + ig * 128 + r0] = lj2;
        }
        __syncthreads();

        // ---- bwd GEMV: W[j][r] = sum_i QT[i][j]*S[i][r]; V += W in place --
        {
            unsigned long long a0 = 0, a1 = 0, a2 = 0, a3 = 0;
            const int j0 = i0;
#pragma unroll 8
            for (int i = 0; i < 48; ++i) {
                const float4 q = *(const float4*)&sm[SO_QT + i * 48 + j0];
                const unsigned long long v = *(const unsigned long long*)&sm[SO_S + i * RST + r0];
                ffma2(a0, splat2(q.x), v);
                ffma2(a1, splat2(q.y), v);
                ffma2(a2, splat2(q.z), v);
                ffma2(a3, splat2(q.w), v);
            }
            unsigned long long acc[4] = {a0, a1, a2, a3};
#pragma unroll
            for (int p = 0; p < 4; ++p) {
                float2* vp = (float2*)&sm[SO_V + (j0 + p) * RST + r0];
                float2 v = *vp;                     // exclusive (j,r) ownership
                float2 w = unpk2(acc[p]);
                v.x += w.x; v.y += w.y;
                *vp = v;
            }
        }
        __syncthreads();

        // ---- scatter (V now holds V+W) + per-row logdet partials ----------
        {
            const int rid = ri[jg];
#pragma unroll
            for (int t = 0; t < 8; ++t) {
                int r = rb + 16 * t;
                out[(size_t)(nbase + r) * NDIMT + rid] = sm[SO_V + jg * RST + r];
            }
            if (tid < ROWS_IT) {
                float s = 0.f;
#pragma unroll
                for (int g = 0; g < 12; ++g) s += sm[SO_LJ + g * 128 + tid];
                g_lj[(size_t)k * NSAMP + nbase + tid] = s;
            }
        }
        __syncthreads();
    }
}

// ---------------------------------------------------------------------------
// Kernel 4: deterministic logdet reduction.
// ---------------------------------------------------------------------------
__global__ void reduce_lj(float* __restrict__ logj) {
    int n = blockIdx.x * blockDim.x + threadIdx.x;
    if (n >= NSAMP) return;
    float s = 0.f;
#pragma unroll
    for (int k = 0; k < NKER; ++k) s += g_lj[(size_t)k * NSAMP + n];
    logj[n] = s;
}

// ---------------------------------------------------------------------------
// Launch
// ---------------------------------------------------------------------------
extern "C" void kernel_launch(void* const* d_in, const int* in_sizes, int n_in,
                              void* d_out, int out_size) {
    const float* data     = (const float*)d_in[0];
    const float* A_raw    = (const float*)d_in[1];
    const float* x0       = (const float*)d_in[2];
    const float* logdx    = (const float*)d_in[3];
    const float* y0       = (const float*)d_in[4];
    const float* logdy    = (const float*)d_in[5];
    const float* logderiv = (const float*)d_in[6];

    float* out  = (float*)d_out;
    float* logj = out + (size_t)NSAMP * NDIMT;

    cudaFuncSetAttribute(fused_kernel,
                         cudaFuncAttributeMaxDynamicSharedMemorySize, SMEM_BYTES);

    orth_kernel<<<NKER, 64>>>(A_raw);
    knots_kernel<<<NTRT / 4, 128>>>(x0, logdx, y0, logdy, logderiv);
    lut_kernel<<<NTRT / 8, 256>>>();
    fused_kernel<<<dim3(NKER, 16), TPB, SMEM_BYTES>>>(data, out);
    reduce_lj<<<(NSAMP + 255) / 256, 256>>>(logj);
}